// round 5
// baseline (speedup 1.0000x reference)
#include <cuda_runtime.h>
#include <cstdint>

// Fixed shapes: pred/target = [4, 8192, 3] fp32
#define NB      4
#define NPTS    8192
#define THREADS 128
#define APT     8                      // a-points per thread (4 f32x2 packs)
#define A_PER_BLOCK (THREADS * APT)    // 1024
#define ACH     8                      // a chunks  (8 * 1024 = 8192)
#define TCH     16                     // target chunks
#define TPCH    512                    // targets per chunk = one shared tile
#define TILE    TPCH
#define NDIRB   (2 * NB)               // 8
#define CTAS_PER_DIRB (ACH * TCH)      // 128

// Scratch (static device allocations — allowed)
__device__ float        g_smin[NDIRB * TCH * NPTS];  // 4 MB partial mins
__device__ float        g_sums[NDIRB];
__device__ unsigned int g_cnt[NDIRB];                // zero-init; reset each replay
__device__ unsigned int g_cnt2;                      // zero-init; reset each replay

typedef unsigned long long u64;

__device__ __forceinline__ u64 pack2(float lo, float hi) {
    u64 r; asm("mov.b64 %0, {%1, %2};" : "=l"(r) : "f"(lo), "f"(hi)); return r;
}
__device__ __forceinline__ void unpack2(u64 v, float& lo, float& hi) {
    asm("mov.b64 {%0, %1}, %2;" : "=f"(lo), "=f"(hi) : "l"(v));
}
// Packed fp32x2 FMA (Blackwell)
__device__ __forceinline__ u64 fma2(u64 a, u64 b, u64 c) {
    u64 d; asm("fma.rn.f32x2 %0, %1, %2, %3;" : "=l"(d) : "l"(a), "l"(b), "l"(c)); return d;
}

__global__ void __launch_bounds__(THREADS, 6)
chamfer_fused_kernel(const float* __restrict__ pred, const float* __restrict__ tgt,
                     float* __restrict__ out) {
    __shared__ float4 sh[TILE * 2];   // [2j]=(qx,qx,qy,qy), [2j+1]=(qz,qz,h,h) = 16.4 KB
    __shared__ int    s_last;
    __shared__ float  s_red[THREADS];

    const int tchunk = blockIdx.x;
    const int achunk = blockIdx.y;
    const int dirb   = blockIdx.z;        // dir*4 + batch
    const int dir    = dirb >> 2;
    const int b      = dirb & 3;

    const float* Ap = (dir == 0 ? pred : tgt) + (size_t)b * NPTS * 3;
    const float* Bp = (dir == 0 ? tgt : pred) + (size_t)b * NPTS * 3;

    const int tid   = threadIdx.x;
    const int abase = achunk * A_PER_BLOCK + tid * APT;

    // Stage this CTA's target tile: pre-duplicated for f32x2 broadcast.
    {
        const int tb = tchunk * TPCH;
        for (int j = tid; j < TILE; j += THREADS) {
            int gj = tb + j;
            float x = Bp[3 * gj + 0];
            float y = Bp[3 * gj + 1];
            float z = Bp[3 * gj + 2];
            float h = 0.5f * fmaf(x, x, fmaf(y, y, z * z));
            sh[2 * j]     = make_float4(x, x, y, y);
            sh[2 * j + 1] = make_float4(z, z, h, h);
        }
    }

    // Register-resident negated a-points, packed 2-per-f32x2.
    u64 nax[APT / 2], nay[APT / 2], naz[APT / 2];
    float mn[APT];
#pragma unroll
    for (int k = 0; k < APT / 2; k++) {
        int i0 = abase + 2 * k;
        float x0 = Ap[3 * i0 + 0], y0 = Ap[3 * i0 + 1], z0 = Ap[3 * i0 + 2];
        float x1 = Ap[3 * i0 + 3], y1 = Ap[3 * i0 + 4], z1 = Ap[3 * i0 + 5];
        nax[k] = pack2(-x0, -x1);
        nay[k] = pack2(-y0, -y1);
        naz[k] = pack2(-z0, -z1);
        mn[2 * k]     = __int_as_float(0x7f800000);
        mn[2 * k + 1] = __int_as_float(0x7f800000);
    }

    __syncthreads();

    const ulonglong2* sp = reinterpret_cast<const ulonglong2*>(sh);
#pragma unroll 4
    for (int j = 0; j < TILE; j++) {
        ulonglong2 v0 = sp[2 * j];       // qx2, qy2 (warp-broadcast LDS.128)
        ulonglong2 v1 = sp[2 * j + 1];   // qz2, h2
        u64 qx2 = v0.x, qy2 = v0.y, qz2 = v1.x, h2 = v1.y;
#pragma unroll
        for (int k = 0; k < APT / 2; k++) {
            u64 s = fma2(naz[k], qz2, h2);
            s = fma2(nay[k], qy2, s);
            s = fma2(nax[k], qx2, s);
            float s0, s1; unpack2(s, s0, s1);
            mn[2 * k]     = fminf(mn[2 * k], s0);
            mn[2 * k + 1] = fminf(mn[2 * k + 1], s1);
        }
    }

    // Publish partial mins:  s = 0.5||b||^2 - a.b  (dist^2 = ||a||^2 + 2s)
    {
        float* dst = &g_smin[((size_t)dirb * TCH + tchunk) * NPTS];
#pragma unroll
        for (int i = 0; i < APT; i++) dst[abase + i] = mn[i];
    }

    // Elect last CTA of this dirb group.
    __threadfence();
    if (tid == 0) {
        unsigned int old = atomicAdd(&g_cnt[dirb], 1u);
        s_last = (old == CTAS_PER_DIRB - 1);
    }
    __syncthreads();
    if (!s_last) return;
    __threadfence();  // acquire all g_smin writes for this dirb

    // Per-dirb tail: combine tchunk mins, add ||a||^2, sum over points.
    const float* base = &g_smin[(size_t)dirb * TCH * NPTS];
    float sum = 0.0f;
    for (int a = tid; a < NPTS; a += THREADS) {
        float s = base[a];
#pragma unroll
        for (int t = 1; t < TCH; t++) s = fminf(s, base[(size_t)t * NPTS + a]);
        float x = Ap[3 * a + 0], y = Ap[3 * a + 1], z = Ap[3 * a + 2];
        sum += fmaf(x, x, fmaf(y, y, z * z)) + 2.0f * s;
    }
    s_red[tid] = sum;
    __syncthreads();
    for (int off = THREADS / 2; off > 0; off >>= 1) {
        if (tid < off) s_red[tid] += s_red[tid + off];
        __syncthreads();
    }

    if (tid == 0) {
        g_sums[dirb] = s_red[0];
        __threadfence();
        unsigned int old2 = atomicAdd(&g_cnt2, 1u);
        if (old2 == NDIRB - 1) {
            __threadfence();
            float total = 0.0f;
#pragma unroll
            for (int d = 0; d < NDIRB; d++) total += g_sums[d];
            *out = total * (1.0f / ((float)NB * (float)NPTS));
            // Reset counters for the next graph replay.
#pragma unroll
            for (int d = 0; d < NDIRB; d++) g_cnt[d] = 0u;
            g_cnt2 = 0u;
            __threadfence();
        }
    }
}

extern "C" void kernel_launch(void* const* d_in, const int* in_sizes, int n_in,
                              void* d_out, int out_size) {
    const float* pred = (const float*)d_in[0];
    const float* tgt  = (const float*)d_in[1];
    float* out = (float*)d_out;
    (void)in_sizes; (void)n_in; (void)out_size;

    dim3 grid(TCH, ACH, NDIRB);   // 16 x 8 x 8 = 1024 CTAs
    chamfer_fused_kernel<<<grid, THREADS>>>(pred, tgt, out);
}

// round 6
// speedup vs baseline: 1.0352x; 1.0352x over previous
#include <cuda_runtime.h>
#include <cstdint>

// Fixed shapes: pred/target = [4, 8192, 3] fp32
#define NB      4
#define NPTS    8192
#define THREADS 128
#define APT     8                      // 4 points packed f32x2 + 4 points scalar
#define A_PER_BLOCK (THREADS * APT)    // 1024
#define ACH     8                      // a chunks  (8 * 1024 = 8192)
#define TCH     8                      // target chunks
#define TPCH    1024                   // targets per chunk = one shared tile
#define TILE    TPCH
#define NDIRB   (2 * NB)               // 8
#define CTAS_PER_DIRB (ACH * TCH)      // 64

__device__ float        g_smin[NDIRB * TCH * NPTS];  // 2 MB partial mins
__device__ float        g_sums[NDIRB];
__device__ unsigned int g_cnt[NDIRB];
__device__ unsigned int g_cnt2;

typedef unsigned long long u64;

__device__ __forceinline__ u64 pack2(float lo, float hi) {
    u64 r; asm("mov.b64 %0, {%1, %2};" : "=l"(r) : "f"(lo), "f"(hi)); return r;
}
__device__ __forceinline__ void unpack2(u64 v, float& lo, float& hi) {
    asm("mov.b64 {%0, %1}, %2;" : "=f"(lo), "=f"(hi) : "l"(v));
}
__device__ __forceinline__ float lo32(u64 v) {
    float f; asm("{ .reg .f32 hi; mov.b64 {%0, hi}, %1; }" : "=f"(f) : "l"(v)); return f;
}
// Packed fp32x2 FMA — executes on the heavy (fp64) pipe, concurrent with scalar FFMA.
__device__ __forceinline__ u64 fma2(u64 a, u64 b, u64 c) {
    u64 d; asm("fma.rn.f32x2 %0, %1, %2, %3;" : "=l"(d) : "l"(a), "l"(b), "l"(c)); return d;
}

__global__ void __launch_bounds__(THREADS, 4)
chamfer_fused_kernel(const float* __restrict__ pred, const float* __restrict__ tgt,
                     float* __restrict__ out) {
    __shared__ float4 sh[TILE * 2];   // [2j]=(qx,qx,qy,qy), [2j+1]=(qz,qz,h,h) = 32 KB
    __shared__ int    s_last;
    __shared__ float  s_red[THREADS];

    const int tchunk = blockIdx.x;
    const int achunk = blockIdx.y;
    const int dirb   = blockIdx.z;        // dir*4 + batch
    const int dir    = dirb >> 2;
    const int b      = dirb & 3;

    const float* Ap = (dir == 0 ? pred : tgt) + (size_t)b * NPTS * 3;
    const float* Bp = (dir == 0 ? tgt : pred) + (size_t)b * NPTS * 3;

    const int tid   = threadIdx.x;
    const int abase = achunk * A_PER_BLOCK + tid * APT;

    // Stage target tile (pre-duplicated for f32x2 broadcast; scalar path reads lo halves).
    {
        const int tb = tchunk * TPCH;
        for (int j = tid; j < TILE; j += THREADS) {
            int gj = tb + j;
            float x = Bp[3 * gj + 0];
            float y = Bp[3 * gj + 1];
            float z = Bp[3 * gj + 2];
            float h = 0.5f * fmaf(x, x, fmaf(y, y, z * z));
            sh[2 * j]     = make_float4(x, x, y, y);
            sh[2 * j + 1] = make_float4(z, z, h, h);
        }
    }

    // Points 0..3: packed (heavy pipe).  Points 4..7: scalar (fma pipe).
    u64 nax[2], nay[2], naz[2];
    float sx[4], sy[4], sz[4];
    float mn[APT];
#pragma unroll
    for (int k = 0; k < 2; k++) {
        int i0 = abase + 2 * k;
        nax[k] = pack2(-Ap[3 * i0 + 0], -Ap[3 * i0 + 3]);
        nay[k] = pack2(-Ap[3 * i0 + 1], -Ap[3 * i0 + 4]);
        naz[k] = pack2(-Ap[3 * i0 + 2], -Ap[3 * i0 + 5]);
    }
#pragma unroll
    for (int i = 0; i < 4; i++) {
        int ii = abase + 4 + i;
        sx[i] = -Ap[3 * ii + 0];
        sy[i] = -Ap[3 * ii + 1];
        sz[i] = -Ap[3 * ii + 2];
    }
#pragma unroll
    for (int i = 0; i < APT; i++) mn[i] = __int_as_float(0x7f800000);

    __syncthreads();

    const ulonglong2* sp = reinterpret_cast<const ulonglong2*>(sh);
#pragma unroll 2
    for (int j = 0; j < TILE; j++) {
        ulonglong2 v0 = sp[2 * j];       // qx2, qy2 (warp-broadcast LDS.128)
        ulonglong2 v1 = sp[2 * j + 1];   // qz2, h2
        u64 qx2 = v0.x, qy2 = v0.y, qz2 = v1.x, h2 = v1.y;

        // Heavy pipe: 6 FFMA2 covering points 0..3
#pragma unroll
        for (int k = 0; k < 2; k++) {
            u64 s = fma2(naz[k], qz2, h2);
            s = fma2(nay[k], qy2, s);
            s = fma2(nax[k], qx2, s);
            float s0, s1; unpack2(s, s0, s1);
            mn[2 * k]     = fminf(mn[2 * k], s0);
            mn[2 * k + 1] = fminf(mn[2 * k + 1], s1);
        }

        // fma pipe: 12 scalar FFMA covering points 4..7 (reuse lo halves, no extra LDS)
        float qx = lo32(qx2), qy = lo32(qy2), qz = lo32(qz2), h = lo32(h2);
#pragma unroll
        for (int i = 0; i < 4; i++) {
            float s = fmaf(sx[i], qx, fmaf(sy[i], qy, fmaf(sz[i], qz, h)));
            mn[4 + i] = fminf(mn[4 + i], s);
        }
    }

    // Publish partial mins:  s = 0.5||b||^2 - a.b  (dist^2 = ||a||^2 + 2s)
    {
        float* dst = &g_smin[((size_t)dirb * TCH + tchunk) * NPTS];
#pragma unroll
        for (int i = 0; i < APT; i++) dst[abase + i] = mn[i];
    }

    __threadfence();
    if (tid == 0) {
        unsigned int old = atomicAdd(&g_cnt[dirb], 1u);
        s_last = (old == CTAS_PER_DIRB - 1);
    }
    __syncthreads();
    if (!s_last) return;
    __threadfence();

    // Per-dirb tail: combine tchunk mins, add ||a||^2, sum over points.
    const float* base = &g_smin[(size_t)dirb * TCH * NPTS];
    float sum = 0.0f;
    for (int a = tid; a < NPTS; a += THREADS) {
        float s = base[a];
#pragma unroll
        for (int t = 1; t < TCH; t++) s = fminf(s, base[(size_t)t * NPTS + a]);
        float x = Ap[3 * a + 0], y = Ap[3 * a + 1], z = Ap[3 * a + 2];
        sum += fmaf(x, x, fmaf(y, y, z * z)) + 2.0f * s;
    }
    s_red[tid] = sum;
    __syncthreads();
    for (int off = THREADS / 2; off > 0; off >>= 1) {
        if (tid < off) s_red[tid] += s_red[tid + off];
        __syncthreads();
    }

    if (tid == 0) {
        g_sums[dirb] = s_red[0];
        __threadfence();
        unsigned int old2 = atomicAdd(&g_cnt2, 1u);
        if (old2 == NDIRB - 1) {
            __threadfence();
            float total = 0.0f;
#pragma unroll
            for (int d = 0; d < NDIRB; d++) total += g_sums[d];
            *out = total * (1.0f / ((float)NB * (float)NPTS));
#pragma unroll
            for (int d = 0; d < NDIRB; d++) g_cnt[d] = 0u;
            g_cnt2 = 0u;
            __threadfence();
        }
    }
}

extern "C" void kernel_launch(void* const* d_in, const int* in_sizes, int n_in,
                              void* d_out, int out_size) {
    const float* pred = (const float*)d_in[0];
    const float* tgt  = (const float*)d_in[1];
    float* out = (float*)d_out;
    (void)in_sizes; (void)n_in; (void)out_size;

    dim3 grid(TCH, ACH, NDIRB);   // 8 x 8 x 8 = 512 CTAs, one wave
    chamfer_fused_kernel<<<grid, THREADS>>>(pred, tgt, out);
}